// round 2
// baseline (speedup 1.0000x reference)
#include <cuda_runtime.h>
#include <math.h>

#define Nn 50000
#define Ee 800000
#define DD 64
#define LRA 0.2f

// ---------------- scratch (device globals: allocation-free rule) ----------------
__device__ float g_P[(size_t)Nn * DD];
__device__ float g_Q[(size_t)Nn * DD];
__device__ float g_edge_m[(size_t)Ee * DD];
__device__ float g_edge_e[Ee];
__device__ float g_rel[Ee];
__device__ float g_erow[Nn];
__device__ float g_denom[Nn];
__device__ float g_numrow[Nn];
__device__ float g_rank[Nn];
__device__ float g_soft[Nn];
__device__ float g_Z;
__device__ int   g_maxbits;

__device__ __forceinline__ float lrelu(float x) { return x > 0.f ? x : LRA * x; }
__device__ __forceinline__ float fixz(float x) { return x == 0.f ? 1e-12f : x; }

// ---------------- K0: zero accumulators ----------------
__global__ void k_zero(float* __restrict__ out) {
    int idx = blockIdx.x * 256 + threadIdx.x;
    if (idx < Nn * DD) out[idx] = 0.f;
    if (idx < Nn) { g_erow[idx] = 0.f; g_denom[idx] = 0.f; g_numrow[idx] = 0.f; }
    if (idx == 0) { g_Z = 0.f; g_maxbits = 0; }
}

// ---------------- K1: node GEMM: C[n][j] = sum_k X[n][k]*a[j][koff+k] ----------------
template <int KOFF, int WHICH>   // WHICH: 0 -> g_P, 1 -> g_Q
__global__ void k_node_gemm(const float* __restrict__ X, const float* __restrict__ a) {
    __shared__ float sx[64][65];
    __shared__ float sw[64][68];
    float* __restrict__ C = WHICH == 0 ? g_P : g_Q;
    int tid = threadIdx.x;
    int tx = tid & 15, ty = tid >> 4;
    int n0 = blockIdx.x * 64;

    for (int i = tid; i < 64 * 64; i += 256) {
        int r = i >> 6, k = i & 63;
        int n = n0 + r;
        sx[r][k] = (n < Nn) ? X[(size_t)n * DD + k] : 0.f;
    }
    for (int i = tid; i < 64 * 64; i += 256) {
        int k = i & 63, j = i >> 6;
        sw[k][j] = a[j * 192 + KOFF + k];
    }
    __syncthreads();

    float acc[4][4] = {};
    int r0 = ty * 4, c0 = tx * 4;
#pragma unroll 16
    for (int k = 0; k < 64; k++) {
        float4 wv = *(const float4*)&sw[k][c0];
#pragma unroll
        for (int i = 0; i < 4; i++) {
            float xv = sx[r0 + i][k];
            acc[i][0] += xv * wv.x; acc[i][1] += xv * wv.y;
            acc[i][2] += xv * wv.z; acc[i][3] += xv * wv.w;
        }
    }
#pragma unroll
    for (int i = 0; i < 4; i++) {
        int n = n0 + r0 + i;
        if (n < Nn)
            *(float4*)&C[(size_t)n * DD + c0] =
                make_float4(acc[i][0], acc[i][1], acc[i][2], acc[i][3]);
    }
}

// ---------------- K2: edge GEMM + attention epilogue ----------------
__global__ void k_edge_gemm(const float* __restrict__ emb, const float* __restrict__ a,
                            const float* __restrict__ a2,
                            const int* __restrict__ src, const int* __restrict__ dst) {
    __shared__ float sx[64][65];
    __shared__ float sw[64][68];
    __shared__ float sa2[64];
    __shared__ int   ssrc[64], sdst[64];
    __shared__ float spw[64];
    int tid = threadIdx.x;
    int tx = tid & 15, ty = tid >> 4;
    size_t e0 = (size_t)blockIdx.x * 64;

    for (int i = tid; i < 64 * 64; i += 256) {
        int r = i >> 6, k = i & 63;
        sx[r][k] = emb[(e0 + r) * DD + k];
    }
    for (int i = tid; i < 64 * 64; i += 256) {
        int k = i & 63, j = i >> 6;
        sw[k][j] = a[j * 192 + 128 + k];
    }
    if (tid < 64) {
        sa2[tid]  = a2[tid];
        ssrc[tid] = src[e0 + tid];
        sdst[tid] = dst[e0 + tid];
    }
    __syncthreads();

    float acc[4][4] = {};
    int r0 = ty * 4, c0 = tx * 4;
#pragma unroll 16
    for (int k = 0; k < 64; k++) {
        float4 wv = *(const float4*)&sw[k][c0];
#pragma unroll
        for (int i = 0; i < 4; i++) {
            float xv = sx[r0 + i][k];
            acc[i][0] += xv * wv.x; acc[i][1] += xv * wv.y;
            acc[i][2] += xv * wv.z; acc[i][3] += xv * wv.w;
        }
    }

    float a2v0 = sa2[c0], a2v1 = sa2[c0 + 1], a2v2 = sa2[c0 + 2], a2v3 = sa2[c0 + 3];
    float pw[4];
#pragma unroll
    for (int i = 0; i < 4; i++) {
        int rl = r0 + i;
        size_t e = e0 + rl;
        int s = ssrc[rl], d = sdst[rl];
        float4 pv = *(const float4*)&g_P[(size_t)s * DD + c0];
        float4 qv = *(const float4*)&g_Q[(size_t)d * DD + c0];
        float v0 = lrelu(acc[i][0] + pv.x + qv.x);
        float v1 = lrelu(acc[i][1] + pv.y + qv.y);
        float v2 = lrelu(acc[i][2] + pv.z + qv.z);
        float v3 = lrelu(acc[i][3] + pv.w + qv.w);
        *(float4*)&g_edge_m[e * DD + c0] = make_float4(v0, v1, v2, v3);
        pw[i] = v0 * a2v0 + v1 * a2v1 + v2 * a2v2 + v3 * a2v3;
    }
#pragma unroll
    for (int m = 8; m >= 1; m >>= 1)
#pragma unroll
        for (int i = 0; i < 4; i++)
            pw[i] += __shfl_xor_sync(0xffffffffu, pw[i], m);
    if (tx == 0)
#pragma unroll
        for (int i = 0; i < 4; i++) spw[r0 + i] = pw[i];
    __syncthreads();

    if (tid < 64) {
        float p = -lrelu(spw[tid]);
        float ee = expf(p);
        g_edge_e[e0 + tid] = ee;
        atomicAdd(&g_erow[sdst[tid]], ee);
    }
}

// ---------------- K3: rel + denom ----------------
__global__ void k_rel(const int* __restrict__ src) {
    int e = blockIdx.x * 256 + threadIdx.x;
    if (e >= Ee) return;
    int s = src[e];
    float rel = g_edge_e[e] / fixz(g_erow[s]);
    g_rel[e] = rel;
    atomicAdd(&g_denom[s], rel);
}

// ---------------- K4: num + num_rowsum ----------------
__global__ void k_num(const int* __restrict__ src, const int* __restrict__ dst,
                      const float* __restrict__ rank_in) {
    int e = blockIdx.x * 256 + threadIdx.x;
    if (e >= Ee) return;
    int s = src[e];
    float num = g_rel[e] * rank_in[s] / fixz(g_denom[s]);
    atomicAdd(&g_numrow[dst[e]], num);
}

// ---------------- K5a: rank_new + global max ----------------
__global__ void k_rank_max() {
    __shared__ float sm[8];
    int idx = blockIdx.x * 256 + threadIdx.x;
    float r = -1e30f;
    if (idx < Nn) {
        r = 0.15f + 0.85f * g_numrow[idx];
        g_rank[idx] = r;
    }
    float v = r;
#pragma unroll
    for (int m = 16; m >= 1; m >>= 1) v = fmaxf(v, __shfl_xor_sync(0xffffffffu, v, m));
    if ((threadIdx.x & 31) == 0) sm[threadIdx.x >> 5] = v;
    __syncthreads();
    if (threadIdx.x < 8) {
        v = sm[threadIdx.x];
#pragma unroll
        for (int m = 4; m >= 1; m >>= 1) v = fmaxf(v, __shfl_xor_sync(0xffu, v, m));
        if (threadIdx.x == 0) atomicMax(&g_maxbits, __float_as_int(v)); // values > 0
    }
}

// ---------------- K5b: exp + global sum ----------------
__global__ void k_softmax_sum() {
    __shared__ float sm[8];
    int idx = blockIdx.x * 256 + threadIdx.x;
    float mx = __int_as_float(g_maxbits);
    float t = 0.f;
    if (idx < Nn) {
        t = expf(g_rank[idx] - mx);
        g_soft[idx] = t;
    }
    float v = t;
#pragma unroll
    for (int m = 16; m >= 1; m >>= 1) v += __shfl_xor_sync(0xffffffffu, v, m);
    if ((threadIdx.x & 31) == 0) sm[threadIdx.x >> 5] = v;
    __syncthreads();
    if (threadIdx.x < 8) {
        v = sm[threadIdx.x];
#pragma unroll
        for (int m = 4; m >= 1; m >>= 1) v += __shfl_xor_sync(0xffu, v, m);
        if (threadIdx.x == 0) atomicAdd(&g_Z, v);
    }
}

// ---------------- K5c: normalize ----------------
__global__ void k_softmax_scale() {
    int idx = blockIdx.x * 256 + threadIdx.x;
    if (idx < Nn) g_soft[idx] = g_soft[idx] / g_Z;
}

// ---------------- K6: weighted feature scatter ----------------
__global__ void k_scatter(const int* __restrict__ src, const int* __restrict__ dst,
                          float* __restrict__ out) {
    int idx = blockIdx.x * 256 + threadIdx.x;   // E*64 = 51.2M < 2^31
    int e = idx >> 6, j = idx & 63;
    float s = g_soft[src[e]] * g_edge_e[e];     // uniform per warp
    atomicAdd(&out[(size_t)dst[e] * DD + j], s * g_edge_m[(size_t)idx]);
}

// ---------------- K7: finalize ----------------
__global__ void k_finalize(float* __restrict__ out) {
    int idx = blockIdx.x * 256 + threadIdx.x;
    if (idx < Nn * DD) {
        int n = idx >> 6;
        float h = out[idx] / fixz(g_erow[n]);
        out[idx] = h > 0.f ? h : expm1f(h);
    }
    if (idx < Nn) out[(size_t)Nn * DD + idx] = g_rank[idx];
}

// ---------------- launcher ----------------
extern "C" void kernel_launch(void* const* d_in, const int* in_sizes, int n_in,
                              void* d_out, int out_size) {
    const float* input   = (const float*)d_in[0];
    const int*   edge    = (const int*)d_in[1];
    const float* emb     = (const float*)d_in[2];
    const float* rank_in = (const float*)d_in[3];
    const float* a       = (const float*)d_in[4];
    const float* a2      = (const float*)d_in[5];
    const int* src = edge;
    const int* dst = edge + Ee;
    float* out = (float*)d_out;

    int nodeBlk = (Nn + 63) / 64;          // 782
    int edgeBlk = Ee / 64;                 // 12500 (E divides 64 exactly)
    int eThrBlk = (Ee + 255) / 256;        // 3125
    int nThrBlk = (Nn + 255) / 256;        // 196
    int zBlk    = (Nn * DD + 255) / 256;   // 12500
    int scatBlk = (Ee * DD) / 256;         // 200000

    k_zero<<<zBlk, 256>>>(out);
    k_node_gemm<0, 0><<<nodeBlk, 256>>>(input, a);
    k_node_gemm<64, 1><<<nodeBlk, 256>>>(input, a);
    k_edge_gemm<<<edgeBlk, 256>>>(emb, a, a2, src, dst);
    k_rel<<<eThrBlk, 256>>>(src);
    k_num<<<eThrBlk, 256>>>(src, dst, rank_in);
    k_rank_max<<<nThrBlk, 256>>>();
    k_softmax_sum<<<nThrBlk, 256>>>();
    k_softmax_scale<<<nThrBlk, 256>>>();
    k_scatter<<<scatBlk, 256>>>(src, dst, out);
    k_finalize<<<zBlk, 256>>>(out);
}

// round 3
// speedup vs baseline: 1.0361x; 1.0361x over previous
#include <cuda_runtime.h>
#include <math.h>

#define Nn 50000
#define Ee 800000
#define DD 64
#define LRA 0.2f

// ---------------- scratch (device globals: allocation-free rule) ----------------
__device__ float g_P[(size_t)Nn * DD];
__device__ float g_Q[(size_t)Nn * DD];
__device__ float g_edge_m[(size_t)Ee * DD];
__device__ float g_edge_e[Ee];
__device__ float g_rel[Ee];
__device__ float g_erow[Nn];
__device__ float g_denom[Nn];
__device__ float g_numrow[Nn];
__device__ float g_rank[Nn];
__device__ float g_soft[Nn];
__device__ float g_Z;
__device__ int   g_maxbits;

__device__ __forceinline__ float lrelu(float x) { return x > 0.f ? x : LRA * x; }
__device__ __forceinline__ float fixz(float x) { return x == 0.f ? 1e-12f : x; }

// ---------------- K0: zero accumulators ----------------
__global__ void k_zero(float* __restrict__ out) {
    int idx = blockIdx.x * 256 + threadIdx.x;
    if (idx < Nn * DD) out[idx] = 0.f;
    if (idx < Nn) { g_erow[idx] = 0.f; g_denom[idx] = 0.f; g_numrow[idx] = 0.f; }
    if (idx == 0) { g_Z = 0.f; g_maxbits = 0; }
}

// ---------------- K1: node GEMM: C[n][j] = sum_k X[n][k]*a[j][KOFF+k] ----------------
// 128-row tile, 256 threads, 8x4 microtile, k unrolled by 4 (all-LDS.128 inner loop).
template <int KOFF, int WHICH>   // WHICH: 0 -> g_P, 1 -> g_Q
__global__ __launch_bounds__(256) void k_node_gemm(const float* __restrict__ X,
                                                   const float* __restrict__ a) {
    __shared__ float sx[128 * 64];   // 32 KB, row-major flat
    __shared__ float sw[64 * 64];    // 16 KB, sw[k*64 + j]
    float* __restrict__ C = WHICH == 0 ? g_P : g_Q;
    int tid = threadIdx.x;
    int tx = tid & 15, ty = tid >> 4;
    int n0 = blockIdx.x * 128;

    // load X tile (coalesced float4 copy, clamp tail rows)
    const float4* Xv = (const float4*)X;
    float4* sxv = (float4*)sx;
    for (int i = tid; i < 128 * 16; i += 256) {
        int r = i >> 4, kq = i & 15;
        int n = n0 + r; if (n >= Nn) n = Nn - 1;
        sxv[i] = Xv[(size_t)n * 16 + kq];
    }
    // load weights transposed: sw[k][j] = a[j][KOFF+k]
    for (int i = tid; i < 64 * 16; i += 256) {
        int j = i & 63, k4 = i >> 6;
        float4 v = *(const float4*)(a + j * 192 + KOFF + k4 * 4);
        sw[(k4 * 4 + 0) * 64 + j] = v.x;
        sw[(k4 * 4 + 1) * 64 + j] = v.y;
        sw[(k4 * 4 + 2) * 64 + j] = v.z;
        sw[(k4 * 4 + 3) * 64 + j] = v.w;
    }
    __syncthreads();

    int r0 = ty * 8, c0 = tx * 4;
    float acc[8][4] = {};
#pragma unroll 4
    for (int k4 = 0; k4 < 16; k4++) {
        float4 w0 = *(const float4*)&sw[(k4 * 4 + 0) * 64 + c0];
        float4 w1 = *(const float4*)&sw[(k4 * 4 + 1) * 64 + c0];
        float4 w2 = *(const float4*)&sw[(k4 * 4 + 2) * 64 + c0];
        float4 w3 = *(const float4*)&sw[(k4 * 4 + 3) * 64 + c0];
#pragma unroll
        for (int i = 0; i < 8; i++) {
            float4 xv = *(const float4*)&sx[(r0 + i) * 64 + k4 * 4];
            acc[i][0] += xv.x * w0.x + xv.y * w1.x + xv.z * w2.x + xv.w * w3.x;
            acc[i][1] += xv.x * w0.y + xv.y * w1.y + xv.z * w2.y + xv.w * w3.y;
            acc[i][2] += xv.x * w0.z + xv.y * w1.z + xv.z * w2.z + xv.w * w3.z;
            acc[i][3] += xv.x * w0.w + xv.y * w1.w + xv.z * w2.w + xv.w * w3.w;
        }
    }
#pragma unroll
    for (int i = 0; i < 8; i++) {
        int n = n0 + r0 + i;
        if (n < Nn)
            *(float4*)&C[(size_t)n * DD + c0] =
                make_float4(acc[i][0], acc[i][1], acc[i][2], acc[i][3]);
    }
}

// ---------------- K2: edge GEMM + attention epilogue ----------------
// 128-edge tile, 8x4 microtile, k unrolled by 4. E = 6250*128 exactly.
__global__ __launch_bounds__(256) void k_edge_gemm(const float* __restrict__ emb,
                                                   const float* __restrict__ a,
                                                   const float* __restrict__ a2,
                                                   const int* __restrict__ src,
                                                   const int* __restrict__ dst) {
    __shared__ float sx[128 * 64];   // 32 KB
    __shared__ float sw[64 * 64];    // 16 KB
    int tid = threadIdx.x;
    int tx = tid & 15, ty = tid >> 4;
    size_t e0 = (size_t)blockIdx.x * 128;

    const float4* embv = (const float4*)emb + e0 * 16;
    float4* sxv = (float4*)sx;
    for (int i = tid; i < 128 * 16; i += 256) sxv[i] = embv[i];
    for (int i = tid; i < 64 * 16; i += 256) {
        int j = i & 63, k4 = i >> 6;
        float4 v = *(const float4*)(a + j * 192 + 128 + k4 * 4);
        sw[(k4 * 4 + 0) * 64 + j] = v.x;
        sw[(k4 * 4 + 1) * 64 + j] = v.y;
        sw[(k4 * 4 + 2) * 64 + j] = v.z;
        sw[(k4 * 4 + 3) * 64 + j] = v.w;
    }
    __syncthreads();

    int r0 = ty * 8, c0 = tx * 4;
    float acc[8][4] = {};
#pragma unroll 4
    for (int k4 = 0; k4 < 16; k4++) {
        float4 w0 = *(const float4*)&sw[(k4 * 4 + 0) * 64 + c0];
        float4 w1 = *(const float4*)&sw[(k4 * 4 + 1) * 64 + c0];
        float4 w2 = *(const float4*)&sw[(k4 * 4 + 2) * 64 + c0];
        float4 w3 = *(const float4*)&sw[(k4 * 4 + 3) * 64 + c0];
#pragma unroll
        for (int i = 0; i < 8; i++) {
            float4 xv = *(const float4*)&sx[(r0 + i) * 64 + k4 * 4];
            acc[i][0] += xv.x * w0.x + xv.y * w1.x + xv.z * w2.x + xv.w * w3.x;
            acc[i][1] += xv.x * w0.y + xv.y * w1.y + xv.z * w2.y + xv.w * w3.y;
            acc[i][2] += xv.x * w0.z + xv.y * w1.z + xv.z * w2.z + xv.w * w3.z;
            acc[i][3] += xv.x * w0.w + xv.y * w1.w + xv.z * w2.w + xv.w * w3.w;
        }
    }

    // epilogue: add P[src]+Q[dst], leakyrelu, store edge_m, reduce powers
    float4 a2v = *(const float4*)(a2 + c0);
    float pw[8];
#pragma unroll
    for (int i = 0; i < 8; i++) {
        int rl = r0 + i;
        size_t e = e0 + rl;
        int s = src[e], d = dst[e];         // warp-uniform across tx -> broadcast
        float4 pv = *(const float4*)&g_P[(size_t)s * DD + c0];
        float4 qv = *(const float4*)&g_Q[(size_t)d * DD + c0];
        float v0 = lrelu(acc[i][0] + pv.x + qv.x);
        float v1 = lrelu(acc[i][1] + pv.y + qv.y);
        float v2 = lrelu(acc[i][2] + pv.z + qv.z);
        float v3 = lrelu(acc[i][3] + pv.w + qv.w);
        *(float4*)&g_edge_m[e * DD + c0] = make_float4(v0, v1, v2, v3);
        pw[i] = v0 * a2v.x + v1 * a2v.y + v2 * a2v.z + v3 * a2v.w;
    }
#pragma unroll
    for (int m = 8; m >= 1; m >>= 1)
#pragma unroll
        for (int i = 0; i < 8; i++)
            pw[i] += __shfl_xor_sync(0xffffffffu, pw[i], m);
    if (tx == 0) {
#pragma unroll
        for (int i = 0; i < 8; i++) {
            size_t e = e0 + r0 + i;
            float p = -lrelu(pw[i]);
            float ee = expf(p);
            g_edge_e[e] = ee;
            atomicAdd(&g_erow[dst[e]], ee);
        }
    }
}

// ---------------- K3: rel + denom ----------------
__global__ void k_rel(const int* __restrict__ src) {
    int e = blockIdx.x * 256 + threadIdx.x;
    if (e >= Ee) return;
    int s = src[e];
    float rel = g_edge_e[e] / fixz(g_erow[s]);
    g_rel[e] = rel;
    atomicAdd(&g_denom[s], rel);
}

// ---------------- K4: num + num_rowsum ----------------
__global__ void k_num(const int* __restrict__ src, const int* __restrict__ dst,
                      const float* __restrict__ rank_in) {
    int e = blockIdx.x * 256 + threadIdx.x;
    if (e >= Ee) return;
    int s = src[e];
    float num = g_rel[e] * rank_in[s] / fixz(g_denom[s]);
    atomicAdd(&g_numrow[dst[e]], num);
}

// ---------------- K5a: rank_new + global max ----------------
__global__ void k_rank_max() {
    __shared__ float sm[8];
    int idx = blockIdx.x * 256 + threadIdx.x;
    float r = -1e30f;
    if (idx < Nn) {
        r = 0.15f + 0.85f * g_numrow[idx];
        g_rank[idx] = r;
    }
    float v = r;
#pragma unroll
    for (int m = 16; m >= 1; m >>= 1) v = fmaxf(v, __shfl_xor_sync(0xffffffffu, v, m));
    if ((threadIdx.x & 31) == 0) sm[threadIdx.x >> 5] = v;
    __syncthreads();
    if (threadIdx.x < 8) {
        v = sm[threadIdx.x];
#pragma unroll
        for (int m = 4; m >= 1; m >>= 1) v = fmaxf(v, __shfl_xor_sync(0xffu, v, m));
        if (threadIdx.x == 0) atomicMax(&g_maxbits, __float_as_int(v)); // values > 0
    }
}

// ---------------- K5b: exp + global sum ----------------
__global__ void k_softmax_sum() {
    __shared__ float sm[8];
    int idx = blockIdx.x * 256 + threadIdx.x;
    float mx = __int_as_float(g_maxbits);
    float t = 0.f;
    if (idx < Nn) {
        t = expf(g_rank[idx] - mx);
        g_soft[idx] = t;
    }
    float v = t;
#pragma unroll
    for (int m = 16; m >= 1; m >>= 1) v += __shfl_xor_sync(0xffffffffu, v, m);
    if ((threadIdx.x & 31) == 0) sm[threadIdx.x >> 5] = v;
    __syncthreads();
    if (threadIdx.x < 8) {
        v = sm[threadIdx.x];
#pragma unroll
        for (int m = 4; m >= 1; m >>= 1) v += __shfl_xor_sync(0xffu, v, m);
        if (threadIdx.x == 0) atomicAdd(&g_Z, v);
    }
}

// ---------------- K5c: normalize ----------------
__global__ void k_softmax_scale() {
    int idx = blockIdx.x * 256 + threadIdx.x;
    if (idx < Nn) g_soft[idx] = g_soft[idx] / g_Z;
}

// ---------------- K6: weighted feature scatter ----------------
__global__ void k_scatter(const int* __restrict__ src, const int* __restrict__ dst,
                          float* __restrict__ out) {
    int idx = blockIdx.x * 256 + threadIdx.x;   // E*64 = 51.2M < 2^31
    int e = idx >> 6, j = idx & 63;
    float s = g_soft[src[e]] * g_edge_e[e];     // uniform per warp
    atomicAdd(&out[(size_t)dst[e] * DD + j], s * g_edge_m[(size_t)idx]);
}

// ---------------- K7: finalize ----------------
__global__ void k_finalize(float* __restrict__ out) {
    int idx = blockIdx.x * 256 + threadIdx.x;
    if (idx < Nn * DD) {
        int n = idx >> 6;
        float h = out[idx] / fixz(g_erow[n]);
        out[idx] = h > 0.f ? h : expm1f(h);
    }
    if (idx < Nn) out[(size_t)Nn * DD + idx] = g_rank[idx];
}

// ---------------- launcher ----------------
extern "C" void kernel_launch(void* const* d_in, const int* in_sizes, int n_in,
                              void* d_out, int out_size) {
    const float* input   = (const float*)d_in[0];
    const int*   edge    = (const int*)d_in[1];
    const float* emb     = (const float*)d_in[2];
    const float* rank_in = (const float*)d_in[3];
    const float* a       = (const float*)d_in[4];
    const float* a2      = (const float*)d_in[5];
    const int* src = edge;
    const int* dst = edge + Ee;
    float* out = (float*)d_out;

    int nodeBlk = (Nn + 127) / 128;        // 391
    int edgeBlk = Ee / 128;                // 6250 (E divides 128 exactly)
    int eThrBlk = (Ee + 255) / 256;        // 3125
    int nThrBlk = (Nn + 255) / 256;        // 196
    int zBlk    = (Nn * DD + 255) / 256;   // 12500
    int scatBlk = (Ee * DD) / 256;         // 200000

    k_zero<<<zBlk, 256>>>(out);
    k_node_gemm<0, 0><<<nodeBlk, 256>>>(input, a);
    k_node_gemm<64, 1><<<nodeBlk, 256>>>(input, a);
    k_edge_gemm<<<edgeBlk, 256>>>(emb, a, a2, src, dst);
    k_rel<<<eThrBlk, 256>>>(src);
    k_num<<<eThrBlk, 256>>>(src, dst, rank_in);
    k_rank_max<<<nThrBlk, 256>>>();
    k_softmax_sum<<<nThrBlk, 256>>>();
    k_softmax_scale<<<nThrBlk, 256>>>();
    k_scatter<<<scatBlk, 256>>>(src, dst, out);
    k_finalize<<<zBlk, 256>>>(out);
}

// round 4
// speedup vs baseline: 1.4725x; 1.4212x over previous
#include <cuda_runtime.h>
#include <math.h>

#define Nn 50000
#define Ee 800000
#define DD 64
#define LRA 0.2f

// ---------------- scratch (device globals: allocation-free rule) ----------------
__device__ float g_P[(size_t)Nn * DD];
__device__ float g_Q[(size_t)Nn * DD];
__device__ float g_edge_m[(size_t)Ee * DD];
__device__ float g_edge_e[Ee];
__device__ float g_rel[Ee];
__device__ float g_erow[Nn];
__device__ float g_denom[Nn];
__device__ float g_numrow[Nn];
__device__ float g_rank[Nn];
__device__ float g_soft[Nn];
__device__ float g_Z;
__device__ int   g_maxbits;

__device__ __forceinline__ float lrelu(float x) { return x > 0.f ? x : LRA * x; }
__device__ __forceinline__ float fixz(float x) { return x == 0.f ? 1e-12f : x; }

// ---------------- K0: zero accumulators ----------------
__global__ void k_zero(float* __restrict__ out) {
    int idx = blockIdx.x * 256 + threadIdx.x;
    if (idx < Nn * DD) out[idx] = 0.f;
    if (idx < Nn) { g_erow[idx] = 0.f; g_denom[idx] = 0.f; g_numrow[idx] = 0.f; }
    if (idx == 0) { g_Z = 0.f; g_maxbits = 0; }
}

// ================= shared GEMM core pieces =================
// tile: 128 rows x 64 cols, 512 threads, 4x4 microtile.
// tx = tid & 15 (16 col-groups of 4), ty = tid >> 4 (32 row-groups of 4).

// ---------------- K1: node GEMM: C[n][j] = sum_k X[n][k]*a[j][KOFF+k] ----------------
template <int KOFF, int WHICH>   // WHICH: 0 -> g_P, 1 -> g_Q
__global__ __launch_bounds__(512, 2) void k_node_gemm(const float* __restrict__ X,
                                                      const float* __restrict__ a) {
    __shared__ float sx[128 * 64];   // 32 KB
    __shared__ float sw[64 * 64];    // 16 KB
    float* __restrict__ C = WHICH == 0 ? g_P : g_Q;
    int tid = threadIdx.x;
    int tx = tid & 15, ty = tid >> 4;
    int n0 = blockIdx.x * 128;

    const float4* Xv = (const float4*)X;
    float4* sxv = (float4*)sx;
    for (int i = tid; i < 128 * 16; i += 512) {
        int r = i >> 4, kq = i & 15;
        int n = n0 + r; if (n >= Nn) n = Nn - 1;
        sxv[i] = Xv[(size_t)n * 16 + kq];
    }
    for (int i = tid; i < 64 * 16; i += 512) {
        int j = i & 63, k4 = i >> 6;
        float4 v = *(const float4*)(a + j * 192 + KOFF + k4 * 4);
        sw[(k4 * 4 + 0) * 64 + j] = v.x;
        sw[(k4 * 4 + 1) * 64 + j] = v.y;
        sw[(k4 * 4 + 2) * 64 + j] = v.z;
        sw[(k4 * 4 + 3) * 64 + j] = v.w;
    }
    __syncthreads();

    int r0 = ty * 4, c0 = tx * 4;
    float acc[4][4] = {};
#pragma unroll 4
    for (int k4 = 0; k4 < 16; k4++) {
        float4 w0 = *(const float4*)&sw[(k4 * 4 + 0) * 64 + c0];
        float4 w1 = *(const float4*)&sw[(k4 * 4 + 1) * 64 + c0];
        float4 w2 = *(const float4*)&sw[(k4 * 4 + 2) * 64 + c0];
        float4 w3 = *(const float4*)&sw[(k4 * 4 + 3) * 64 + c0];
#pragma unroll
        for (int i = 0; i < 4; i++) {
            float4 xv = *(const float4*)&sx[(r0 + i) * 64 + k4 * 4];
            acc[i][0] += xv.x * w0.x + xv.y * w1.x + xv.z * w2.x + xv.w * w3.x;
            acc[i][1] += xv.x * w0.y + xv.y * w1.y + xv.z * w2.y + xv.w * w3.y;
            acc[i][2] += xv.x * w0.z + xv.y * w1.z + xv.z * w2.z + xv.w * w3.z;
            acc[i][3] += xv.x * w0.w + xv.y * w1.w + xv.z * w2.w + xv.w * w3.w;
        }
    }
#pragma unroll
    for (int i = 0; i < 4; i++) {
        int n = n0 + r0 + i;
        if (n < Nn)
            *(float4*)&C[(size_t)n * DD + c0] =
                make_float4(acc[i][0], acc[i][1], acc[i][2], acc[i][3]);
    }
}

// ---------------- K2: edge GEMM + attention epilogue ----------------
// E = 6250*128 exactly (no tail).
__global__ __launch_bounds__(512, 2) void k_edge_gemm(const float* __restrict__ emb,
                                                      const float* __restrict__ a,
                                                      const float* __restrict__ a2,
                                                      const int* __restrict__ src,
                                                      const int* __restrict__ dst) {
    __shared__ float sx[128 * 64];   // 32 KB
    __shared__ float sw[64 * 64];    // 16 KB
    int tid = threadIdx.x;
    int tx = tid & 15, ty = tid >> 4;
    size_t e0 = (size_t)blockIdx.x * 128;

    const float4* embv = (const float4*)emb + e0 * 16;
    float4* sxv = (float4*)sx;
    for (int i = tid; i < 128 * 16; i += 512) sxv[i] = embv[i];
    for (int i = tid; i < 64 * 16; i += 512) {
        int j = i & 63, k4 = i >> 6;
        float4 v = *(const float4*)(a + j * 192 + 128 + k4 * 4);
        sw[(k4 * 4 + 0) * 64 + j] = v.x;
        sw[(k4 * 4 + 1) * 64 + j] = v.y;
        sw[(k4 * 4 + 2) * 64 + j] = v.z;
        sw[(k4 * 4 + 3) * 64 + j] = v.w;
    }
    __syncthreads();

    int r0 = ty * 4, c0 = tx * 4;
    float acc[4][4] = {};
#pragma unroll 4
    for (int k4 = 0; k4 < 16; k4++) {
        float4 w0 = *(const float4*)&sw[(k4 * 4 + 0) * 64 + c0];
        float4 w1 = *(const float4*)&sw[(k4 * 4 + 1) * 64 + c0];
        float4 w2 = *(const float4*)&sw[(k4 * 4 + 2) * 64 + c0];
        float4 w3 = *(const float4*)&sw[(k4 * 4 + 3) * 64 + c0];
#pragma unroll
        for (int i = 0; i < 4; i++) {
            float4 xv = *(const float4*)&sx[(r0 + i) * 64 + k4 * 4];
            acc[i][0] += xv.x * w0.x + xv.y * w1.x + xv.z * w2.x + xv.w * w3.x;
            acc[i][1] += xv.x * w0.y + xv.y * w1.y + xv.z * w2.y + xv.w * w3.y;
            acc[i][2] += xv.x * w0.z + xv.y * w1.z + xv.z * w2.z + xv.w * w3.z;
            acc[i][3] += xv.x * w0.w + xv.y * w1.w + xv.z * w2.w + xv.w * w3.w;
        }
    }

    // epilogue: add P[src]+Q[dst], leakyrelu, store edge_m, reduce powers over tx
    float4 a2v = *(const float4*)(a2 + c0);
    float pw[4];
#pragma unroll
    for (int i = 0; i < 4; i++) {
        int rl = r0 + i;
        size_t e = e0 + rl;
        int s = src[e], d = dst[e];   // warp-uniform across tx -> broadcast
        float4 pv = *(const float4*)&g_P[(size_t)s * DD + c0];
        float4 qv = *(const float4*)&g_Q[(size_t)d * DD + c0];
        float v0 = lrelu(acc[i][0] + pv.x + qv.x);
        float v1 = lrelu(acc[i][1] + pv.y + qv.y);
        float v2 = lrelu(acc[i][2] + pv.z + qv.z);
        float v3 = lrelu(acc[i][3] + pv.w + qv.w);
        *(float4*)&g_edge_m[e * DD + c0] = make_float4(v0, v1, v2, v3);
        pw[i] = v0 * a2v.x + v1 * a2v.y + v2 * a2v.z + v3 * a2v.w;
    }
#pragma unroll
    for (int m = 8; m >= 1; m >>= 1)
#pragma unroll
        for (int i = 0; i < 4; i++)
            pw[i] += __shfl_xor_sync(0xffffffffu, pw[i], m);   // reduces over tx (16-lane half)
    if (tx == 0) {
#pragma unroll
        for (int i = 0; i < 4; i++) {
            size_t e = e0 + r0 + i;
            float p = -lrelu(pw[i]);
            float ee = expf(p);
            g_edge_e[e] = ee;
            atomicAdd(&g_erow[dst[e]], ee);
        }
    }
}

// ---------------- K3: rel + denom ----------------
__global__ void k_rel(const int* __restrict__ src) {
    int e = blockIdx.x * 256 + threadIdx.x;
    if (e >= Ee) return;
    int s = src[e];
    float rel = g_edge_e[e] / fixz(g_erow[s]);
    g_rel[e] = rel;
    atomicAdd(&g_denom[s], rel);
}

// ---------------- K4: num + num_rowsum ----------------
__global__ void k_num(const int* __restrict__ src, const int* __restrict__ dst,
                      const float* __restrict__ rank_in) {
    int e = blockIdx.x * 256 + threadIdx.x;
    if (e >= Ee) return;
    int s = src[e];
    float num = g_rel[e] * rank_in[s] / fixz(g_denom[s]);
    atomicAdd(&g_numrow[dst[e]], num);
}

// ---------------- K5a: rank_new + global max ----------------
__global__ void k_rank_max() {
    __shared__ float sm[8];
    int idx = blockIdx.x * 256 + threadIdx.x;
    float r = -1e30f;
    if (idx < Nn) {
        r = 0.15f + 0.85f * g_numrow[idx];
        g_rank[idx] = r;
    }
    float v = r;
#pragma unroll
    for (int m = 16; m >= 1; m >>= 1) v = fmaxf(v, __shfl_xor_sync(0xffffffffu, v, m));
    if ((threadIdx.x & 31) == 0) sm[threadIdx.x >> 5] = v;
    __syncthreads();
    if (threadIdx.x < 8) {
        v = sm[threadIdx.x];
#pragma unroll
        for (int m = 4; m >= 1; m >>= 1) v = fmaxf(v, __shfl_xor_sync(0xffu, v, m));
        if (threadIdx.x == 0) atomicMax(&g_maxbits, __float_as_int(v)); // values > 0
    }
}

// ---------------- K5b: exp + global sum ----------------
__global__ void k_softmax_sum() {
    __shared__ float sm[8];
    int idx = blockIdx.x * 256 + threadIdx.x;
    float mx = __int_as_float(g_maxbits);
    float t = 0.f;
    if (idx < Nn) {
        t = expf(g_rank[idx] - mx);
        g_soft[idx] = t;
    }
    float v = t;
#pragma unroll
    for (int m = 16; m >= 1; m >>= 1) v += __shfl_xor_sync(0xffffffffu, v, m);
    if ((threadIdx.x & 31) == 0) sm[threadIdx.x >> 5] = v;
    __syncthreads();
    if (threadIdx.x < 8) {
        v = sm[threadIdx.x];
#pragma unroll
        for (int m = 4; m >= 1; m >>= 1) v += __shfl_xor_sync(0xffu, v, m);
        if (threadIdx.x == 0) atomicAdd(&g_Z, v);
    }
}

// ---------------- K5c: normalize ----------------
__global__ void k_softmax_scale() {
    int idx = blockIdx.x * 256 + threadIdx.x;
    if (idx < Nn) g_soft[idx] = g_soft[idx] / g_Z;
}

// ---------------- K6: weighted feature scatter (vectorized red.v4) ----------------
// out[dst][g*4..g*4+3] += soft[src]*edge_e[e] * edge_m[e][g*4..]
__global__ void k_scatter(const int* __restrict__ src, const int* __restrict__ dst,
                          float* __restrict__ out) {
    int idx = blockIdx.x * 256 + threadIdx.x;   // E*16 = 12.8M
    int e = idx >> 4, g = idx & 15;
    float s = g_soft[src[e]] * g_edge_e[e];     // uniform across the 16-lane group
    float4 m = *(const float4*)&g_edge_m[((size_t)e << 6) + g * 4];
    float* p = &out[((size_t)dst[e] << 6) + g * 4];
    asm volatile("red.global.add.v4.f32 [%0], {%1,%2,%3,%4};"
                 :: "l"(p), "f"(s * m.x), "f"(s * m.y), "f"(s * m.z), "f"(s * m.w)
                 : "memory");
}

// ---------------- K7: finalize ----------------
__global__ void k_finalize(float* __restrict__ out) {
    int idx = blockIdx.x * 256 + threadIdx.x;
    if (idx < Nn * DD) {
        int n = idx >> 6;
        float h = out[idx] / fixz(g_erow[n]);
        out[idx] = h > 0.f ? h : expm1f(h);
    }
    if (idx < Nn) out[(size_t)Nn * DD + idx] = g_rank[idx];
}

// ---------------- launcher ----------------
extern "C" void kernel_launch(void* const* d_in, const int* in_sizes, int n_in,
                              void* d_out, int out_size) {
    const float* input   = (const float*)d_in[0];
    const int*   edge    = (const int*)d_in[1];
    const float* emb     = (const float*)d_in[2];
    const float* rank_in = (const float*)d_in[3];
    const float* a       = (const float*)d_in[4];
    const float* a2      = (const float*)d_in[5];
    const int* src = edge;
    const int* dst = edge + Ee;
    float* out = (float*)d_out;

    int nodeBlk = (Nn + 127) / 128;        // 391
    int edgeBlk = Ee / 128;                // 6250
    int eThrBlk = (Ee + 255) / 256;        // 3125
    int nThrBlk = (Nn + 255) / 256;        // 196
    int zBlk    = (Nn * DD + 255) / 256;   // 12500
    int scatBlk = (Ee * 16) / 256;         // 50000

    k_zero<<<zBlk, 256>>>(out);
    k_node_gemm<0, 0><<<nodeBlk, 512>>>(input, a);
    k_node_gemm<64, 1><<<nodeBlk, 512>>>(input, a);
    k_edge_gemm<<<edgeBlk, 512>>>(emb, a, a2, src, dst);
    k_rel<<<eThrBlk, 256>>>(src);
    k_num<<<eThrBlk, 256>>>(src, dst, rank_in);
    k_rank_max<<<nThrBlk, 256>>>();
    k_softmax_sum<<<nThrBlk, 256>>>();
    k_softmax_scale<<<nThrBlk, 256>>>();
    k_scatter<<<scatBlk, 256>>>(src, dst, out);
    k_finalize<<<zBlk, 256>>>(out);
}